// round 10
// baseline (speedup 1.0000x reference)
#include <cuda_runtime.h>

// Problem constants (fixed by the dataset)
#define NN 100000   // nodes
#define DD 128      // feature dim
#define NEt 2       // edge types
#define EE 800000   // edges per etype
#define NC 768      // fused output cols = NEt * 3 * DD

// ---- scratch (static __device__ arrays: sanctioned workaround, no allocs) ----
__device__ float g_FW[DD * NC];                      // fused weights [k][c], c = e*384 + p*128 + m (p: 0=K,1=Q,2=V)
__device__ float g_FB[NC];                           // fused biases
__device__ float g_QKV[NN * NC];                     // 307 MB
__device__ float g_Wh[NEt * NN * DD];                // 102 MB, attention outputs per etype
__device__ float g_hsum[NN * DD];                    // 51 MB, cross-etype accumulated messages
__device__ int   g_deg[NEt * NN];

// ---------------- zero accumulators ----------------
__global__ void k_zero() {
    int tid = blockIdx.x * blockDim.x + threadIdx.x;
    int stride = gridDim.x * blockDim.x;
    float4* h4 = reinterpret_cast<float4*>(g_hsum);
    const int n4 = NN * DD / 4;
    float4 z = make_float4(0.f, 0.f, 0.f, 0.f);
    for (int i = tid; i < n4; i += stride) h4[i] = z;
    for (int i = tid; i < NEt * NN; i += stride) g_deg[i] = 0;
}

// ---------------- weight fusion: FW[i][c] = sum_j Wt[e][i][j] * P[e][j][m] ----------------
// grid = 12 blocks: e = b/6, p = (b%6)/2, half = b%2 (half of the 128 m-cols)
__global__ __launch_bounds__(256) void k_fuse(
    const float* __restrict__ Wt, const float* __restrict__ Kw,
    const float* __restrict__ Qw, const float* __restrict__ Vw)
{
    __shared__ float At[32][132];   // transposed Wt tile: At[j][i]
    __shared__ float Bt[32][64];    // P tile: Bt[j][m]
    int bid = blockIdx.x;
    int e = bid / 6;
    int r = bid % 6;
    int p = r >> 1;
    int half = r & 1;
    const float* A = Wt + e * (DD * DD);
    const float* B = (p == 0 ? Kw : (p == 1 ? Qw : Vw)) + e * (DD * DD);
    int tid = threadIdx.x;
    int i0 = (tid >> 4) * 8;
    int m0 = (tid & 15) * 4;

    float acc[8][4];
#pragma unroll
    for (int i = 0; i < 8; ++i)
#pragma unroll
        for (int j = 0; j < 4; ++j) acc[i][j] = 0.f;

    for (int jt = 0; jt < 4; ++jt) {
        int j0 = jt * 32;
#pragma unroll
        for (int it = 0; it < 4; ++it) {        // A tile: 128 rows x 32 cols, transposed store
            int idx = tid + 256 * it;
            int row = idx >> 3;
            int c4 = idx & 7;
            float4 v = *reinterpret_cast<const float4*>(A + row * DD + j0 + c4 * 4);
            At[c4 * 4 + 0][row] = v.x;
            At[c4 * 4 + 1][row] = v.y;
            At[c4 * 4 + 2][row] = v.z;
            At[c4 * 4 + 3][row] = v.w;
        }
#pragma unroll
        for (int it = 0; it < 2; ++it) {        // B tile: 32 rows x 64 cols
            int idx = tid + 256 * it;
            int row = idx >> 4;
            int c4 = idx & 15;
            *reinterpret_cast<float4*>(&Bt[row][c4 * 4]) =
                *reinterpret_cast<const float4*>(B + (j0 + row) * DD + half * 64 + c4 * 4);
        }
        __syncthreads();
#pragma unroll
        for (int jj = 0; jj < 32; ++jj) {
            float a[8], b[4];
            *reinterpret_cast<float4*>(&a[0]) = *reinterpret_cast<float4*>(&At[jj][i0]);
            *reinterpret_cast<float4*>(&a[4]) = *reinterpret_cast<float4*>(&At[jj][i0 + 4]);
            *reinterpret_cast<float4*>(&b[0]) = *reinterpret_cast<float4*>(&Bt[jj][m0]);
#pragma unroll
            for (int i = 0; i < 8; ++i)
#pragma unroll
                for (int j = 0; j < 4; ++j) acc[i][j] = fmaf(a[i], b[j], acc[i][j]);
        }
        __syncthreads();
    }
    int cbase = e * 384 + p * 128 + half * 64 + m0;
#pragma unroll
    for (int i = 0; i < 8; ++i) {
        float4 v = make_float4(acc[i][0], acc[i][1], acc[i][2], acc[i][3]);
        *reinterpret_cast<float4*>(&g_FW[(i0 + i) * NC + cbase]) = v;
    }
}

// ---------------- fused bias: FB[c] = Pb[m] + sum_j bt[e][j] * P[e][j][m] ----------------
__global__ void k_fuse_bias(const float* __restrict__ bt,
                            const float* __restrict__ Kw, const float* __restrict__ Kb,
                            const float* __restrict__ Qw, const float* __restrict__ Qb,
                            const float* __restrict__ Vw, const float* __restrict__ Vb) {
    int c = blockIdx.x * blockDim.x + threadIdx.x;
    if (c >= NC) return;
    int e = c / 384;
    int r = c % 384;
    int p = r / 128;
    int m = r % 128;
    const float* Pw = (p == 0 ? Kw : (p == 1 ? Qw : Vw)) + e * DD * DD;
    const float* Pb = (p == 0 ? Kb : (p == 1 ? Qb : Vb)) + e * DD;
    float acc = Pb[m];
    for (int j = 0; j < DD; ++j) acc += bt[e * DD + j] * Pw[j * DD + m];
    g_FB[c] = acc;
}

// ---------------- main GEMM: QKV[n][c] = feat[n][:] @ FW[:][c] + FB[c] ----------------
// BM=128, BN=128, BK=16; 256 threads, 8x8 microtile -> FMA-balanced vs LDS
#define BM 128
#define BN 128
#define BK 16
__global__ __launch_bounds__(256) void k_gemm(const float* __restrict__ A) {
    __shared__ float As[2][BK][BM + 4];   // transposed: As[k][m]; +4 keeps 16B alignment (528B rows)
    __shared__ float Bs[2][BK][BN];
    int tid = threadIdx.x;
    int m_base = blockIdx.x * BM;
    int n_base = blockIdx.y * BN;
    int tm = tid >> 4;        // 0..15, row group of 8
    int tn = tid & 15;        // 0..15, col group of 8
    // A tile loads: 128 rows x 16 k = 512 float4, 2 per thread
    int arow = tid >> 2;      // 0..63 (+64 second iter)
    int ak4 = tid & 3;        // k-group of 4
    // B tile loads: 16 rows x 128 cols = 512 float4, 2 per thread
    int brow = tid >> 5;      // 0..7 (+8 second iter)
    int bc4 = tid & 31;       // col-group of 4

    float acc[8][8] = {};

    // prologue: tile kt = 0
    {
#pragma unroll
        for (int it = 0; it < 2; ++it) {
            int row = arow + it * 64;
            int gm = m_base + row;
            float4 v = make_float4(0.f, 0.f, 0.f, 0.f);
            if (gm < NN) v = *reinterpret_cast<const float4*>(A + (long)gm * DD + ak4 * 4);
            As[0][ak4 * 4 + 0][row] = v.x;
            As[0][ak4 * 4 + 1][row] = v.y;
            As[0][ak4 * 4 + 2][row] = v.z;
            As[0][ak4 * 4 + 3][row] = v.w;
        }
#pragma unroll
        for (int it = 0; it < 2; ++it) {
            int row = brow + it * 8;
            *reinterpret_cast<float4*>(&Bs[0][row][bc4 * 4]) =
                *reinterpret_cast<const float4*>(&g_FW[row * NC + n_base + bc4 * 4]);
        }
    }
    __syncthreads();

#pragma unroll
    for (int kt = 0; kt < 8; ++kt) {
        int cur = kt & 1;
        float4 pa[2];
        float4 pb[2];
        if (kt < 7) {
            int k0 = (kt + 1) * BK;
#pragma unroll
            for (int it = 0; it < 2; ++it) {
                int row = arow + it * 64;
                int gm = m_base + row;
                pa[it] = make_float4(0.f, 0.f, 0.f, 0.f);
                if (gm < NN) pa[it] = *reinterpret_cast<const float4*>(A + (long)gm * DD + k0 + ak4 * 4);
            }
#pragma unroll
            for (int it = 0; it < 2; ++it) {
                int row = brow + it * 8;
                pb[it] = *reinterpret_cast<const float4*>(&g_FW[(k0 + row) * NC + n_base + bc4 * 4]);
            }
        }
#pragma unroll
        for (int kk = 0; kk < BK; ++kk) {
            float a[8], b[8];
            *reinterpret_cast<float4*>(&a[0]) = *reinterpret_cast<float4*>(&As[cur][kk][tm * 8]);
            *reinterpret_cast<float4*>(&a[4]) = *reinterpret_cast<float4*>(&As[cur][kk][tm * 8 + 4]);
            *reinterpret_cast<float4*>(&b[0]) = *reinterpret_cast<float4*>(&Bs[cur][kk][tn * 8]);
            *reinterpret_cast<float4*>(&b[4]) = *reinterpret_cast<float4*>(&Bs[cur][kk][tn * 8 + 4]);
#pragma unroll
            for (int i = 0; i < 8; ++i)
#pragma unroll
                for (int j = 0; j < 8; ++j) acc[i][j] = fmaf(a[i], b[j], acc[i][j]);
        }
        if (kt < 7) {
            int nxt = cur ^ 1;
#pragma unroll
            for (int it = 0; it < 2; ++it) {
                int row = arow + it * 64;
                As[nxt][ak4 * 4 + 0][row] = pa[it].x;
                As[nxt][ak4 * 4 + 1][row] = pa[it].y;
                As[nxt][ak4 * 4 + 2][row] = pa[it].z;
                As[nxt][ak4 * 4 + 3][row] = pa[it].w;
            }
#pragma unroll
            for (int it = 0; it < 2; ++it)
                *reinterpret_cast<float4*>(&Bs[nxt][brow + it * 8][bc4 * 4]) = pb[it];
            __syncthreads();
        }
    }

    float bias[8];
    *reinterpret_cast<float4*>(&bias[0]) = *reinterpret_cast<const float4*>(&g_FB[n_base + tn * 8]);
    *reinterpret_cast<float4*>(&bias[4]) = *reinterpret_cast<const float4*>(&g_FB[n_base + tn * 8 + 4]);
#pragma unroll
    for (int i = 0; i < 8; ++i) {
        int gm = m_base + tm * 8 + i;
        if (gm < NN) {
            float* orow = g_QKV + (long)gm * NC + n_base + tn * 8;
            float4 v0 = make_float4(acc[i][0] + bias[0], acc[i][1] + bias[1],
                                    acc[i][2] + bias[2], acc[i][3] + bias[3]);
            float4 v1 = make_float4(acc[i][4] + bias[4], acc[i][5] + bias[5],
                                    acc[i][6] + bias[6], acc[i][7] + bias[7]);
            *reinterpret_cast<float4*>(orow) = v0;
            *reinterpret_cast<float4*>(orow + 4) = v1;
        }
    }
}

// ---------------- per-node cross-head attention: warp per (node, etype) ----------------
__global__ void k_attn() {
    int gw = (blockIdx.x * blockDim.x + threadIdx.x) >> 5;
    int lane = threadIdx.x & 31;
    int n = gw >> 1;
    int e = gw & 1;
    if (n >= NN) return;
    const float* base = g_QKV + (long)n * NC + e * 384;
    float kx[4], qx[4], vx[4];
#pragma unroll
    for (int g = 0; g < 4; ++g) kx[g] = __ldg(base + g * 32 + lane);
#pragma unroll
    for (int h = 0; h < 4; ++h) qx[h] = __ldg(base + 128 + h * 32 + lane);
#pragma unroll
    for (int g = 0; g < 4; ++g) vx[g] = __ldg(base + 256 + g * 32 + lane);

    float s[4][4];
#pragma unroll
    for (int h = 0; h < 4; ++h)
#pragma unroll
        for (int g = 0; g < 4; ++g) {
            float pr = qx[h] * kx[g];
#pragma unroll
            for (int o = 16; o > 0; o >>= 1) pr += __shfl_xor_sync(0xffffffffu, pr, o);
            s[h][g] = pr * 0.17677669529663689f;   // 1/sqrt(32)
        }

    float* outp = g_Wh + ((long)e * NN + n) * DD;
#pragma unroll
    for (int h = 0; h < 4; ++h) {
        float mx = fmaxf(fmaxf(s[h][0], s[h][1]), fmaxf(s[h][2], s[h][3]));
        float e0 = __expf(s[h][0] - mx);
        float e1 = __expf(s[h][1] - mx);
        float e2 = __expf(s[h][2] - mx);
        float e3 = __expf(s[h][3] - mx);
        float inv = 1.0f / (e0 + e1 + e2 + e3);
        float o_val = (e0 * vx[0] + e1 * vx[1] + e2 * vx[2] + e3 * vx[3]) * inv;
        outp[h * 32 + lane] = o_val;
    }
}

// ---------------- in-degree count ----------------
__global__ void k_deg(const int* __restrict__ dst) {
    int idx = blockIdx.x * blockDim.x + threadIdx.x;
    if (idx >= NEt * EE) return;
    int e = idx / EE;
    atomicAdd(&g_deg[e * NN + dst[idx]], 1);
}

// ---------------- scatter-mean: warp per edge, lane per float4 ----------------
__global__ void k_scatter(const int* __restrict__ src, const int* __restrict__ dst) {
    long gt = (long)blockIdx.x * blockDim.x + threadIdx.x;
    int gw = (int)(gt >> 5);
    int lane = threadIdx.x & 31;
    if (gw >= NEt * EE) return;
    int e = gw / EE;

    // lane 0 fetches indices + degree, broadcast to the warp
    int s = 0, d = 0; float w = 0.f;
    if (lane == 0) {
        s = __ldg(src + gw);
        d = __ldg(dst + gw);
        int dg = g_deg[e * NN + d];
        w = 1.0f / (float)(dg > 1 ? dg : 1);
    }
    s = __shfl_sync(0xffffffffu, s, 0);
    d = __shfl_sync(0xffffffffu, d, 0);
    w = __shfl_sync(0xffffffffu, w, 0);

    const float4* wp = reinterpret_cast<const float4*>(g_Wh + ((long)e * NN + s) * DD);
    float4 v = __ldg(wp + lane);
    float4 vv = make_float4(v.x * w, v.y * w, v.z * w, v.w * w);
    float4* hp = reinterpret_cast<float4*>(g_hsum + (long)d * DD) + lane;
#if defined(__CUDA_ARCH__) && (__CUDA_ARCH__ >= 900)
    atomicAdd(hp, vv);                       // sm_90+ 128-bit vector atomic -> RED.v4
#else
    atomicAdd(&hp->x, vv.x);
    atomicAdd(&hp->y, vv.y);
    atomicAdd(&hp->z, vv.z);
    atomicAdd(&hp->w, vv.w);
#endif
}

// ---------------- residual + LayerNorm: warp per node ----------------
__global__ void k_final(const float* __restrict__ feat, const float* __restrict__ ln_g,
                        const float* __restrict__ ln_b, float* __restrict__ out) {
    int gw = (blockIdx.x * blockDim.x + threadIdx.x) >> 5;
    int lane = threadIdx.x & 31;
    if (gw >= NN) return;
    const float4* f4 = reinterpret_cast<const float4*>(feat + (long)gw * DD);
    const float4* h4 = reinterpret_cast<const float4*>(g_hsum + (long)gw * DD);
    float4 f = f4[lane];
    float4 hs = h4[lane];
    float4 h = make_float4(f.x + hs.x, f.y + hs.y, f.z + hs.z, f.w + hs.w);

    float s1 = h.x + h.y + h.z + h.w;
#pragma unroll
    for (int o = 16; o > 0; o >>= 1) s1 += __shfl_xor_sync(0xffffffffu, s1, o);
    float mu = s1 * (1.0f / 128.0f);

    float dx = h.x - mu, dy = h.y - mu, dz = h.z - mu, dw = h.w - mu;
    float s2 = dx * dx + dy * dy + dz * dz + dw * dw;
#pragma unroll
    for (int o = 16; o > 0; o >>= 1) s2 += __shfl_xor_sync(0xffffffffu, s2, o);
    float rstd = rsqrtf(s2 * (1.0f / 128.0f) + 1e-5f);

    float4 g = reinterpret_cast<const float4*>(ln_g)[lane];
    float4 b = reinterpret_cast<const float4*>(ln_b)[lane];
    float4 o;
    o.x = dx * rstd * g.x + b.x;
    o.y = dy * rstd * g.y + b.y;
    o.z = dz * rstd * g.z + b.z;
    o.w = dw * rstd * g.w + b.w;
    reinterpret_cast<float4*>(out + (long)gw * DD)[lane] = o;
}

extern "C" void kernel_launch(void* const* d_in, const int* in_sizes, int n_in,
                              void* d_out, int out_size) {
    const float* feat = (const float*)d_in[0];
    const int* src = (const int*)d_in[1];
    const int* dst = (const int*)d_in[2];
    const float* Wt = (const float*)d_in[3];
    const float* bt = (const float*)d_in[4];
    const float* Kw = (const float*)d_in[5];
    const float* Kb = (const float*)d_in[6];
    const float* Qw = (const float*)d_in[7];
    const float* Qb = (const float*)d_in[8];
    const float* Vw = (const float*)d_in[9];
    const float* Vb = (const float*)d_in[10];
    const float* ln_g = (const float*)d_in[11];
    const float* ln_b = (const float*)d_in[12];
    float* out = (float*)d_out;

    k_zero<<<2048, 256>>>();
    k_fuse<<<12, 256>>>(Wt, Kw, Qw, Vw);
    k_fuse_bias<<<3, 256>>>(bt, Kw, Kb, Qw, Qb, Vw, Vb);
    k_gemm<<<dim3((NN + BM - 1) / BM, NC / BN), 256>>>(feat);
    k_attn<<<(NN * NEt * 32) / 256, 256>>>();
    k_deg<<<(NEt * EE + 255) / 256, 256>>>(dst);
    k_scatter<<<(NEt * EE * 32) / 256, 256>>>(src, dst);
    k_final<<<(NN * 32) / 256, 256>>>(feat, ln_g, ln_b, out);
}

// round 14
// speedup vs baseline: 1.3924x; 1.3924x over previous
#include <cuda_runtime.h>
#include <cstdint>

// Problem constants (fixed by the dataset)
#define NN 100000   // nodes
#define DD 128      // feature dim
#define NEt 2       // edge types
#define EE 800000   // edges per etype
#define NC 768      // fused output cols = NEt * 3 * DD

// ---- scratch (static __device__ arrays: sanctioned workaround, no allocs) ----
__device__ float g_FW[DD * NC];                      // fused weights [k][c]
__device__ float g_FB[NC];                           // fused biases
__device__ float g_QKV[NN * NC];                     // 307 MB
__device__ float g_Wh[NEt * NN * DD];                // 102 MB
__device__ float g_hsum[NN * DD];                    // 51 MB
__device__ int   g_deg[NEt * NN];

// ---------------- zero accumulators ----------------
__global__ void k_zero() {
    int tid = blockIdx.x * blockDim.x + threadIdx.x;
    int stride = gridDim.x * blockDim.x;
    float4* h4 = reinterpret_cast<float4*>(g_hsum);
    const int n4 = NN * DD / 4;
    float4 z = make_float4(0.f, 0.f, 0.f, 0.f);
    for (int i = tid; i < n4; i += stride) h4[i] = z;
    for (int i = tid; i < NEt * NN; i += stride) g_deg[i] = 0;
}

// ---------------- weight fusion: FW[i][c] = sum_j Wt[e][i][j] * P[e][j][m] ----------------
__global__ __launch_bounds__(256) void k_fuse(
    const float* __restrict__ Wt, const float* __restrict__ Kw,
    const float* __restrict__ Qw, const float* __restrict__ Vw)
{
    __shared__ float At[32][132];
    __shared__ float Bt[32][64];
    int bid = blockIdx.x;
    int e = bid / 6;
    int r = bid % 6;
    int p = r >> 1;
    int half = r & 1;
    const float* A = Wt + e * (DD * DD);
    const float* B = (p == 0 ? Kw : (p == 1 ? Qw : Vw)) + e * (DD * DD);
    int tid = threadIdx.x;
    int i0 = (tid >> 4) * 8;
    int m0 = (tid & 15) * 4;

    float acc[8][4];
#pragma unroll
    for (int i = 0; i < 8; ++i)
#pragma unroll
        for (int j = 0; j < 4; ++j) acc[i][j] = 0.f;

    for (int jt = 0; jt < 4; ++jt) {
        int j0 = jt * 32;
#pragma unroll
        for (int it = 0; it < 4; ++it) {
            int idx = tid + 256 * it;
            int row = idx >> 3;
            int c4 = idx & 7;
            float4 v = *reinterpret_cast<const float4*>(A + row * DD + j0 + c4 * 4);
            At[c4 * 4 + 0][row] = v.x;
            At[c4 * 4 + 1][row] = v.y;
            At[c4 * 4 + 2][row] = v.z;
            At[c4 * 4 + 3][row] = v.w;
        }
#pragma unroll
        for (int it = 0; it < 2; ++it) {
            int idx = tid + 256 * it;
            int row = idx >> 4;
            int c4 = idx & 15;
            *reinterpret_cast<float4*>(&Bt[row][c4 * 4]) =
                *reinterpret_cast<const float4*>(B + (j0 + row) * DD + half * 64 + c4 * 4);
        }
        __syncthreads();
#pragma unroll
        for (int jj = 0; jj < 32; ++jj) {
            float a[8], b[4];
            *reinterpret_cast<float4*>(&a[0]) = *reinterpret_cast<float4*>(&At[jj][i0]);
            *reinterpret_cast<float4*>(&a[4]) = *reinterpret_cast<float4*>(&At[jj][i0 + 4]);
            *reinterpret_cast<float4*>(&b[0]) = *reinterpret_cast<float4*>(&Bt[jj][m0]);
#pragma unroll
            for (int i = 0; i < 8; ++i)
#pragma unroll
                for (int j = 0; j < 4; ++j) acc[i][j] = fmaf(a[i], b[j], acc[i][j]);
        }
        __syncthreads();
    }
    int cbase = e * 384 + p * 128 + half * 64 + m0;
#pragma unroll
    for (int i = 0; i < 8; ++i) {
        float4 v = make_float4(acc[i][0], acc[i][1], acc[i][2], acc[i][3]);
        *reinterpret_cast<float4*>(&g_FW[(i0 + i) * NC + cbase]) = v;
    }
}

// ---------------- fused bias ----------------
__global__ void k_fuse_bias(const float* __restrict__ bt,
                            const float* __restrict__ Kw, const float* __restrict__ Kb,
                            const float* __restrict__ Qw, const float* __restrict__ Qb,
                            const float* __restrict__ Vw, const float* __restrict__ Vb) {
    int c = blockIdx.x * blockDim.x + threadIdx.x;
    if (c >= NC) return;
    int e = c / 384;
    int r = c % 384;
    int p = r / 128;
    int m = r % 128;
    const float* Pw = (p == 0 ? Kw : (p == 1 ? Qw : Vw)) + e * DD * DD;
    const float* Pb = (p == 0 ? Kb : (p == 1 ? Qb : Vb)) + e * DD;
    float acc = Pb[m];
    for (int j = 0; j < DD; ++j) acc += bt[e * DD + j] * Pw[j * DD + m];
    g_FB[c] = acc;
}

// ---------------- main GEMM (tf32 tensor cores) ----------------
// QKV[n][c] = feat[n][:] @ FW[:][c] + FB[c]
// BM=128, BN=128, BK=16; 256 threads = 8 warps as 2(M)x4(N), warp tile 64x32.
// mma.sync.aligned.m16n8k8.row.col.f32.tf32.tf32.f32
#define BM 128
#define BN 128
#define BK 16
#define A_STRIDE 20    // 128x16 A tile, padded: (r*20+c) mod 32 covers all banks
#define B_STRIDE 136   // 16x128 B tile, padded: (c*136+q) mod 32 = c*8+q covers all banks

__device__ __forceinline__ uint32_t f2tf(float x) {
    uint32_t r;
    asm("cvt.rna.tf32.f32 %0, %1;" : "=r"(r) : "f"(x));
    return r;
}

__global__ __launch_bounds__(256) void k_gemm(const float* __restrict__ A) {
    __shared__ __align__(16) uint32_t As[2][BM][A_STRIDE];
    __shared__ __align__(16) uint32_t Bs[2][BK][B_STRIDE];
    int tid = threadIdx.x;
    int warp = tid >> 5;
    int lane = tid & 31;
    int wm = (warp & 1) * 64;     // warp M offset (2 warps in M)
    int wn = (warp >> 1) * 32;    // warp N offset (4 warps in N)
    int m_base = blockIdx.x * BM;
    int n_base = blockIdx.y * BN;
    int fr = lane >> 2;           // fragment row-group 0..7
    int fc = lane & 3;            // fragment col-group 0..3

    // gmem load indexing (A: 512 float4, 2/thread; B: 512 float4, 2/thread)
    int arow = tid >> 2;          // 0..63 (+64 second iter)
    int ak4 = tid & 3;
    int brow = tid >> 5;          // 0..7 (+8 second iter)
    int bc4 = tid & 31;

    float acc[4][4][4];           // [mt][nt][reg]
#pragma unroll
    for (int mt = 0; mt < 4; ++mt)
#pragma unroll
        for (int nt = 0; nt < 4; ++nt)
#pragma unroll
            for (int k = 0; k < 4; ++k) acc[mt][nt][k] = 0.f;

    // prologue: tile kt = 0
    {
#pragma unroll
        for (int it = 0; it < 2; ++it) {
            int row = arow + it * 64;
            int gm = m_base + row;
            float4 v = make_float4(0.f, 0.f, 0.f, 0.f);
            if (gm < NN) v = *reinterpret_cast<const float4*>(A + (long)gm * DD + ak4 * 4);
            uint32_t* p = &As[0][row][ak4 * 4];
            *reinterpret_cast<uint4*>(p) = make_uint4(f2tf(v.x), f2tf(v.y), f2tf(v.z), f2tf(v.w));
        }
#pragma unroll
        for (int it = 0; it < 2; ++it) {
            int row = brow + it * 8;
            float4 v = *reinterpret_cast<const float4*>(&g_FW[row * NC + n_base + bc4 * 4]);
            uint32_t* p = &Bs[0][row][bc4 * 4];
            *reinterpret_cast<uint4*>(p) = make_uint4(f2tf(v.x), f2tf(v.y), f2tf(v.z), f2tf(v.w));
        }
    }
    __syncthreads();

#pragma unroll
    for (int kt = 0; kt < 8; ++kt) {
        int cur = kt & 1;
        float4 pa[2];
        float4 pb[2];
        if (kt < 7) {
            int k0 = (kt + 1) * BK;
#pragma unroll
            for (int it = 0; it < 2; ++it) {
                int row = arow + it * 64;
                int gm = m_base + row;
                pa[it] = make_float4(0.f, 0.f, 0.f, 0.f);
                if (gm < NN) pa[it] = *reinterpret_cast<const float4*>(A + (long)gm * DD + k0 + ak4 * 4);
            }
#pragma unroll
            for (int it = 0; it < 2; ++it) {
                int row = brow + it * 8;
                pb[it] = *reinterpret_cast<const float4*>(&g_FW[(k0 + row) * NC + n_base + bc4 * 4]);
            }
        }

        // two k=8 chunks per BK=16 tile
#pragma unroll
        for (int ks = 0; ks < 2; ++ks) {
            int k0 = ks * 8;
            uint32_t af[4][4];
#pragma unroll
            for (int mt = 0; mt < 4; ++mt) {
                int mrow = wm + mt * 16;
                af[mt][0] = As[cur][mrow + fr][k0 + fc];
                af[mt][1] = As[cur][mrow + fr + 8][k0 + fc];
                af[mt][2] = As[cur][mrow + fr][k0 + fc + 4];
                af[mt][3] = As[cur][mrow + fr + 8][k0 + fc + 4];
            }
            uint32_t bf[4][2];
#pragma unroll
            for (int nt = 0; nt < 4; ++nt) {
                int ncol = wn + nt * 8 + fr;
                bf[nt][0] = Bs[cur][k0 + fc][ncol];
                bf[nt][1] = Bs[cur][k0 + fc + 4][ncol];
            }
#pragma unroll
            for (int mt = 0; mt < 4; ++mt)
#pragma unroll
                for (int nt = 0; nt < 4; ++nt) {
                    asm volatile(
                        "mma.sync.aligned.m16n8k8.row.col.f32.tf32.tf32.f32 "
                        "{%0,%1,%2,%3}, {%4,%5,%6,%7}, {%8,%9}, {%0,%1,%2,%3};"
                        : "+f"(acc[mt][nt][0]), "+f"(acc[mt][nt][1]),
                          "+f"(acc[mt][nt][2]), "+f"(acc[mt][nt][3])
                        : "r"(af[mt][0]), "r"(af[mt][1]), "r"(af[mt][2]), "r"(af[mt][3]),
                          "r"(bf[nt][0]), "r"(bf[nt][1]));
                }
        }

        if (kt < 7) {
            int nxt = cur ^ 1;
#pragma unroll
            for (int it = 0; it < 2; ++it) {
                int row = arow + it * 64;
                uint32_t* p = &As[nxt][row][ak4 * 4];
                *reinterpret_cast<uint4*>(p) =
                    make_uint4(f2tf(pa[it].x), f2tf(pa[it].y), f2tf(pa[it].z), f2tf(pa[it].w));
            }
#pragma unroll
            for (int it = 0; it < 2; ++it) {
                int row = brow + it * 8;
                uint32_t* p = &Bs[nxt][row][bc4 * 4];
                *reinterpret_cast<uint4*>(p) =
                    make_uint4(f2tf(pb[it].x), f2tf(pb[it].y), f2tf(pb[it].z), f2tf(pb[it].w));
            }
            __syncthreads();
        }
    }

    // epilogue: D fragment c0/c1 at (row=fr, col=2*fc,2*fc+1), c2/c3 at row=fr+8
#pragma unroll
    for (int mt = 0; mt < 4; ++mt) {
#pragma unroll
        for (int nt = 0; nt < 4; ++nt) {
            int gcol = n_base + wn + nt * 8 + fc * 2;
            float2 bias = *reinterpret_cast<const float2*>(&g_FB[gcol]);
            int gm0 = m_base + wm + mt * 16 + fr;
            if (gm0 < NN) {
                float2 v = make_float2(acc[mt][nt][0] + bias.x, acc[mt][nt][1] + bias.y);
                *reinterpret_cast<float2*>(&g_QKV[(long)gm0 * NC + gcol]) = v;
            }
            int gm1 = gm0 + 8;
            if (gm1 < NN) {
                float2 v = make_float2(acc[mt][nt][2] + bias.x, acc[mt][nt][3] + bias.y);
                *reinterpret_cast<float2*>(&g_QKV[(long)gm1 * NC + gcol]) = v;
            }
        }
    }
}

// ---------------- per-node cross-head attention: warp per (node, etype) ----------------
__global__ void k_attn() {
    int gw = (blockIdx.x * blockDim.x + threadIdx.x) >> 5;
    int lane = threadIdx.x & 31;
    int n = gw >> 1;
    int e = gw & 1;
    if (n >= NN) return;
    const float* base = g_QKV + (long)n * NC + e * 384;
    float kx[4], qx[4], vx[4];
#pragma unroll
    for (int g = 0; g < 4; ++g) kx[g] = __ldg(base + g * 32 + lane);
#pragma unroll
    for (int h = 0; h < 4; ++h) qx[h] = __ldg(base + 128 + h * 32 + lane);
#pragma unroll
    for (int g = 0; g < 4; ++g) vx[g] = __ldg(base + 256 + g * 32 + lane);

    float s[4][4];
#pragma unroll
    for (int h = 0; h < 4; ++h)
#pragma unroll
        for (int g = 0; g < 4; ++g) {
            float pr = qx[h] * kx[g];
#pragma unroll
            for (int o = 16; o > 0; o >>= 1) pr += __shfl_xor_sync(0xffffffffu, pr, o);
            s[h][g] = pr * 0.17677669529663689f;   // 1/sqrt(32)
        }

    float* outp = g_Wh + ((long)e * NN + n) * DD;
#pragma unroll
    for (int h = 0; h < 4; ++h) {
        float mx = fmaxf(fmaxf(s[h][0], s[h][1]), fmaxf(s[h][2], s[h][3]));
        float e0 = __expf(s[h][0] - mx);
        float e1 = __expf(s[h][1] - mx);
        float e2 = __expf(s[h][2] - mx);
        float e3 = __expf(s[h][3] - mx);
        float inv = 1.0f / (e0 + e1 + e2 + e3);
        float o_val = (e0 * vx[0] + e1 * vx[1] + e2 * vx[2] + e3 * vx[3]) * inv;
        outp[h * 32 + lane] = o_val;
    }
}

// ---------------- in-degree count ----------------
__global__ void k_deg(const int* __restrict__ dst) {
    int idx = blockIdx.x * blockDim.x + threadIdx.x;
    if (idx >= NEt * EE) return;
    int e = idx / EE;
    atomicAdd(&g_deg[e * NN + dst[idx]], 1);
}

// ---------------- scatter-mean: warp per edge, lane per float4 ----------------
__global__ void k_scatter(const int* __restrict__ src, const int* __restrict__ dst) {
    long gt = (long)blockIdx.x * blockDim.x + threadIdx.x;
    int gw = (int)(gt >> 5);
    int lane = threadIdx.x & 31;
    if (gw >= NEt * EE) return;
    int e = gw / EE;

    int s = 0, d = 0; float w = 0.f;
    if (lane == 0) {
        s = __ldg(src + gw);
        d = __ldg(dst + gw);
        int dg = g_deg[e * NN + d];
        w = 1.0f / (float)(dg > 1 ? dg : 1);
    }
    s = __shfl_sync(0xffffffffu, s, 0);
    d = __shfl_sync(0xffffffffu, d, 0);
    w = __shfl_sync(0xffffffffu, w, 0);

    const float4* wp = reinterpret_cast<const float4*>(g_Wh + ((long)e * NN + s) * DD);
    float4 v = __ldg(wp + lane);
    float4 vv = make_float4(v.x * w, v.y * w, v.z * w, v.w * w);
    float4* hp = reinterpret_cast<float4*>(g_hsum + (long)d * DD) + lane;
#if defined(__CUDA_ARCH__) && (__CUDA_ARCH__ >= 900)
    atomicAdd(hp, vv);
#else
    atomicAdd(&hp->x, vv.x);
    atomicAdd(&hp->y, vv.y);
    atomicAdd(&hp->z, vv.z);
    atomicAdd(&hp->w, vv.w);
#endif
}

// ---------------- residual + LayerNorm: warp per node ----------------
__global__ void k_final(const float* __restrict__ feat, const float* __restrict__ ln_g,
                        const float* __restrict__ ln_b, float* __restrict__ out) {
    int gw = (blockIdx.x * blockDim.x + threadIdx.x) >> 5;
    int lane = threadIdx.x & 31;
    if (gw >= NN) return;
    const float4* f4 = reinterpret_cast<const float4*>(feat + (long)gw * DD);
    const float4* h4 = reinterpret_cast<const float4*>(g_hsum + (long)gw * DD);
    float4 f = f4[lane];
    float4 hs = h4[lane];
    float4 h = make_float4(f.x + hs.x, f.y + hs.y, f.z + hs.z, f.w + hs.w);

    float s1 = h.x + h.y + h.z + h.w;
#pragma unroll
    for (int o = 16; o > 0; o >>= 1) s1 += __shfl_xor_sync(0xffffffffu, s1, o);
    float mu = s1 * (1.0f / 128.0f);

    float dx = h.x - mu, dy = h.y - mu, dz = h.z - mu, dw = h.w - mu;
    float s2 = dx * dx + dy * dy + dz * dz + dw * dw;
#pragma unroll
    for (int o = 16; o > 0; o >>= 1) s2 += __shfl_xor_sync(0xffffffffu, s2, o);
    float rstd = rsqrtf(s2 * (1.0f / 128.0f) + 1e-5f);

    float4 g = reinterpret_cast<const float4*>(ln_g)[lane];
    float4 b = reinterpret_cast<const float4*>(ln_b)[lane];
    float4 o;
    o.x = dx * rstd * g.x + b.x;
    o.y = dy * rstd * g.y + b.y;
    o.z = dz * rstd * g.z + b.z;
    o.w = dw * rstd * g.w + b.w;
    reinterpret_cast<float4*>(out + (long)gw * DD)[lane] = o;
}

extern "C" void kernel_launch(void* const* d_in, const int* in_sizes, int n_in,
                              void* d_out, int out_size) {
    const float* feat = (const float*)d_in[0];
    const int* src = (const int*)d_in[1];
    const int* dst = (const int*)d_in[2];
    const float* Wt = (const float*)d_in[3];
    const float* bt = (const float*)d_in[4];
    const float* Kw = (const float*)d_in[5];
    const float* Kb = (const float*)d_in[6];
    const float* Qw = (const float*)d_in[7];
    const float* Qb = (const float*)d_in[8];
    const float* Vw = (const float*)d_in[9];
    const float* Vb = (const float*)d_in[10];
    const float* ln_g = (const float*)d_in[11];
    const float* ln_b = (const float*)d_in[12];
    float* out = (float*)d_out;

    k_zero<<<2048, 256>>>();
    k_fuse<<<12, 256>>>(Wt, Kw, Qw, Vw);
    k_fuse_bias<<<3, 256>>>(bt, Kw, Kb, Qw, Qb, Vw, Vb);
    k_gemm<<<dim3((NN + BM - 1) / BM, NC / BN), 256>>>(feat);
    k_attn<<<(NN * NEt * 32) / 256, 256>>>();
    k_deg<<<(NEt * EE + 255) / 256, 256>>>(dst);
    k_scatter<<<(NEt * EE * 32) / 256, 256>>>(src, dst);
    k_final<<<(NN * 32) / 256, 256>>>(feat, ln_g, ln_b, out);
}